// round 2
// baseline (speedup 1.0000x reference)
#include <cuda_runtime.h>
#include <cstdint>

// ---------------------------------------------------------------------------
// LiquidNeuralNetwork: y0 = x@Win+bin; 32 fixed DOPRI5 steps of
// f(y)=tanh(y@W1+b1)@W2+b2; out = yT@Wout+bout.
// One CTA = 64 rows, fully SMEM-resident state, fp32 SIMT matmuls.
// ---------------------------------------------------------------------------

#define LNN_L      64
#define LNN_DIN    14
#define LNN_DOUT   3
#define LNN_R      64      // rows per CTA
#define LNN_P      68      // padded pitch (row-dim) in floats
#define LNN_NT     256     // threads per CTA
#define LNN_NSTEPS 32
#define LNN_ARR    (LNN_L * LNN_P)   // 4352 floats per [64][68] array

// SMEM float offsets
#define OFF_Y    0
#define OFF_K    (OFF_Y + LNN_ARR)            // k1..k6: OFF_K + i*LNN_ARR
#define OFF_U    (OFF_K + 6 * LNN_ARR)
#define OFF_T    (OFF_U + LNN_ARR)
#define OFF_W1   (OFF_T + LNN_ARR)
#define OFF_W2   (OFF_W1 + LNN_L * LNN_L)
#define OFF_WIN  (OFF_W2 + LNN_L * LNN_L)
#define OFF_WOUT (OFF_WIN + LNN_DIN * LNN_L)
#define OFF_B1   (OFF_WOUT + LNN_L * LNN_DOUT)
#define OFF_B2   (OFF_B1 + LNN_L)
#define OFF_BIN  (OFF_B2 + LNN_L)
#define OFF_BOUT (OFF_BIN + LNN_L)
#define OFF_X    (OFF_BOUT + 4)
#define SMEM_FLOATS (OFF_X + LNN_R * LNN_DIN)
#define SMEM_BYTES  (SMEM_FLOATS * 4)

__device__ __forceinline__ void fma4(float4& a, float s, const float4& v) {
    a.x = fmaf(s, v.x, a.x);
    a.y = fmaf(s, v.y, a.y);
    a.z = fmaf(s, v.z, a.z);
    a.w = fmaf(s, v.w, a.w);
}

__device__ __forceinline__ float fast_tanh(float x) {
    float ax = fabsf(x);
    float e  = __expf(-2.0f * ax);               // in (0, 1]
    float t  = __fdividef(1.0f - e, 1.0f + e);
    return copysignf(t, x);
}

// acc[a].{x..w} = sum_k src[k][r0+b] * W[k][j0+a]
__device__ __forceinline__ void mm64(const float* __restrict__ src,
                                     const float* __restrict__ W,
                                     int r0, int j0, float4 acc[4]) {
    acc[0] = make_float4(0.f, 0.f, 0.f, 0.f);
    acc[1] = make_float4(0.f, 0.f, 0.f, 0.f);
    acc[2] = make_float4(0.f, 0.f, 0.f, 0.f);
    acc[3] = make_float4(0.f, 0.f, 0.f, 0.f);
#pragma unroll 8
    for (int k = 0; k < LNN_L; ++k) {
        float4 yv = *reinterpret_cast<const float4*>(src + k * LNN_P + r0);
        float4 wv = *reinterpret_cast<const float4*>(W + k * LNN_L + j0);
        fma4(acc[0], wv.x, yv);
        fma4(acc[1], wv.y, yv);
        fma4(acc[2], wv.z, yv);
        fma4(acc[3], wv.w, yv);
    }
}

// dst = tanh(src@W1 + b1) @ W2 + b2  (dst, src, tt are [64][P] transposed bufs)
__device__ __forceinline__ void lnn_feval(const float* __restrict__ src,
                                          float* __restrict__ dst,
                                          float* __restrict__ tt,
                                          const float* __restrict__ w1,
                                          const float* __restrict__ w2,
                                          float4 b1v, float4 b2v,
                                          int r0, int j0) {
    __syncthreads();   // src fully written by all threads
    float4 acc[4];
    mm64(src, w1, r0, j0, acc);
    {
        float bb[4] = {b1v.x, b1v.y, b1v.z, b1v.w};
#pragma unroll
        for (int a = 0; a < 4; ++a) {
            float4 v = acc[a];
            v.x = fast_tanh(v.x + bb[a]);
            v.y = fast_tanh(v.y + bb[a]);
            v.z = fast_tanh(v.z + bb[a]);
            v.w = fast_tanh(v.w + bb[a]);
            *reinterpret_cast<float4*>(tt + (j0 + a) * LNN_P + r0) = v;
        }
    }
    __syncthreads();   // tt fully written
    mm64(tt, w2, r0, j0, acc);
    {
        float bb[4] = {b2v.x, b2v.y, b2v.z, b2v.w};
#pragma unroll
        for (int a = 0; a < 4; ++a) {
            float4 v = acc[a];
            v.x += bb[a]; v.y += bb[a]; v.z += bb[a]; v.w += bb[a];
            *reinterpret_cast<float4*>(dst + (j0 + a) * LNN_P + r0) = v;
        }
    }
}

__global__ __launch_bounds__(LNN_NT)
void lnn2276_kernel(const float* __restrict__ x,
                    const float* __restrict__ ts,
                    const float* __restrict__ gWin, const float* __restrict__ gbin,
                    const float* __restrict__ gW1,  const float* __restrict__ gb1,
                    const float* __restrict__ gW2,  const float* __restrict__ gb2,
                    const float* __restrict__ gWout, const float* __restrict__ gbout,
                    float* __restrict__ out, int B) {
    extern __shared__ float sm[];
    const int t  = threadIdx.x;
    const int rg = t & 15;
    const int cg = t >> 4;
    const int r0 = rg * 4;
    const int j0 = cg * 4;
    const int rowbase = blockIdx.x * LNN_R;

    // ---- cooperative loads into SMEM ----
    {
        float4* d1 = reinterpret_cast<float4*>(sm + OFF_W1);
        const float4* s1 = reinterpret_cast<const float4*>(gW1);
        for (int i = t; i < LNN_L * LNN_L / 4; i += LNN_NT) d1[i] = s1[i];
        float4* d2 = reinterpret_cast<float4*>(sm + OFF_W2);
        const float4* s2 = reinterpret_cast<const float4*>(gW2);
        for (int i = t; i < LNN_L * LNN_L / 4; i += LNN_NT) d2[i] = s2[i];
        float4* dwi = reinterpret_cast<float4*>(sm + OFF_WIN);
        const float4* swi = reinterpret_cast<const float4*>(gWin);
        for (int i = t; i < LNN_DIN * LNN_L / 4; i += LNN_NT) dwi[i] = swi[i];
        float4* dwo = reinterpret_cast<float4*>(sm + OFF_WOUT);
        const float4* swo = reinterpret_cast<const float4*>(gWout);
        for (int i = t; i < LNN_L * LNN_DOUT / 4; i += LNN_NT) dwo[i] = swo[i];
        if (t < LNN_L) {
            sm[OFF_B1 + t]  = gb1[t];
            sm[OFF_B2 + t]  = gb2[t];
            sm[OFF_BIN + t] = gbin[t];
        }
        if (t < LNN_DOUT) sm[OFF_BOUT + t] = gbout[t];

        int nrows = B - rowbase;
        if (nrows >= LNN_R) {
            const float4* sx = reinterpret_cast<const float4*>(x + (size_t)rowbase * LNN_DIN);
            float4* dx = reinterpret_cast<float4*>(sm + OFF_X);
            for (int i = t; i < LNN_R * LNN_DIN / 4; i += LNN_NT) dx[i] = sx[i];
        } else {
            for (int i = t; i < LNN_R * LNN_DIN; i += LNN_NT) {
                int r = i / LNN_DIN;
                sm[OFF_X + i] = (r < nrows) ? x[(size_t)rowbase * LNN_DIN + i] : 0.0f;
            }
        }
    }
    __syncthreads();

    const float dt = (ts[1] - ts[0]) * (1.0f / (float)LNN_NSTEPS);
    float* yb = sm + OFF_Y;
    float* ub = sm + OFF_U;
    float* tb = sm + OFF_T;
    const float* w1 = sm + OFF_W1;
    const float* w2 = sm + OFF_W2;
    const float4 b1v = *reinterpret_cast<const float4*>(sm + OFF_B1 + j0);
    const float4 b2v = *reinterpret_cast<const float4*>(sm + OFF_B2 + j0);

    // ---- y0 = x @ Win + bin, stored transposed ----
    {
        float4 acc[4];
        acc[0] = make_float4(0.f, 0.f, 0.f, 0.f);
        acc[1] = make_float4(0.f, 0.f, 0.f, 0.f);
        acc[2] = make_float4(0.f, 0.f, 0.f, 0.f);
        acc[3] = make_float4(0.f, 0.f, 0.f, 0.f);
#pragma unroll
        for (int k = 0; k < LNN_DIN; ++k) {
            float4 wv = *reinterpret_cast<const float4*>(sm + OFF_WIN + k * LNN_L + j0);
            float4 xv;
            xv.x = sm[OFF_X + (r0 + 0) * LNN_DIN + k];
            xv.y = sm[OFF_X + (r0 + 1) * LNN_DIN + k];
            xv.z = sm[OFF_X + (r0 + 2) * LNN_DIN + k];
            xv.w = sm[OFF_X + (r0 + 3) * LNN_DIN + k];
            fma4(acc[0], wv.x, xv);
            fma4(acc[1], wv.y, xv);
            fma4(acc[2], wv.z, xv);
            fma4(acc[3], wv.w, xv);
        }
        float bb[4] = {sm[OFF_BIN + j0], sm[OFF_BIN + j0 + 1],
                       sm[OFF_BIN + j0 + 2], sm[OFF_BIN + j0 + 3]};
#pragma unroll
        for (int a = 0; a < 4; ++a) {
            float4 v = acc[a];
            v.x += bb[a]; v.y += bb[a]; v.z += bb[a]; v.w += bb[a];
            *reinterpret_cast<float4*>(yb + (j0 + a) * LNN_P + r0) = v;
        }
    }

    // DOPRI5 tableau (double-computed, rounded once to fp32)
    const float A2c[1] = {(float)(1.0 / 5.0)};
    const float A3c[2] = {(float)(3.0 / 40.0), (float)(9.0 / 40.0)};
    const float A4c[3] = {(float)(44.0 / 45.0), (float)(-56.0 / 15.0), (float)(32.0 / 9.0)};
    const float A5c[4] = {(float)(19372.0 / 6561.0), (float)(-25360.0 / 2187.0),
                          (float)(64448.0 / 6561.0), (float)(-212.0 / 729.0)};
    const float A6c[5] = {(float)(9017.0 / 3168.0), (float)(-355.0 / 33.0),
                          (float)(46732.0 / 5247.0), (float)(49.0 / 176.0),
                          (float)(-5103.0 / 18656.0)};
    const float Bc[5]  = {(float)(35.0 / 384.0), (float)(500.0 / 1113.0),
                          (float)(125.0 / 192.0), (float)(-2187.0 / 6784.0),
                          (float)(11.0 / 84.0)};
    const int   Bki[5] = {0, 2, 3, 4, 5};

    // u = y + dt * sum_{i<n} coef[i]*k_i   (per-thread 4x4 block, no sync needed)
    auto combine = [&](float* dst, const float* coef, int n) {
#pragma unroll
        for (int a = 0; a < 4; ++a) {
            int j = j0 + a;
            float4 v = *reinterpret_cast<const float4*>(yb + j * LNN_P + r0);
#pragma unroll
            for (int i = 0; i < n; ++i) {
                float4 kv = *reinterpret_cast<const float4*>(
                    sm + OFF_K + i * LNN_ARR + j * LNN_P + r0);
                fma4(v, dt * coef[i], kv);
            }
            *reinterpret_cast<float4*>(dst + j * LNN_P + r0) = v;
        }
    };

#pragma unroll 1
    for (int step = 0; step < LNN_NSTEPS; ++step) {
        lnn_feval(yb, sm + OFF_K + 0 * LNN_ARR, tb, w1, w2, b1v, b2v, r0, j0);  // k1
        combine(ub, A2c, 1);
        lnn_feval(ub, sm + OFF_K + 1 * LNN_ARR, tb, w1, w2, b1v, b2v, r0, j0);  // k2
        combine(ub, A3c, 2);
        lnn_feval(ub, sm + OFF_K + 2 * LNN_ARR, tb, w1, w2, b1v, b2v, r0, j0);  // k3
        combine(ub, A4c, 3);
        lnn_feval(ub, sm + OFF_K + 3 * LNN_ARR, tb, w1, w2, b1v, b2v, r0, j0);  // k4
        combine(ub, A5c, 4);
        lnn_feval(ub, sm + OFF_K + 4 * LNN_ARR, tb, w1, w2, b1v, b2v, r0, j0);  // k5
        combine(ub, A6c, 5);
        lnn_feval(ub, sm + OFF_K + 5 * LNN_ARR, tb, w1, w2, b1v, b2v, r0, j0);  // k6
        // y += dt*(B1 k1 + B3 k3 + B4 k4 + B5 k5 + B6 k6)
#pragma unroll
        for (int a = 0; a < 4; ++a) {
            int j = j0 + a;
            float4 v = *reinterpret_cast<const float4*>(yb + j * LNN_P + r0);
#pragma unroll
            for (int i = 0; i < 5; ++i) {
                float4 kv = *reinterpret_cast<const float4*>(
                    sm + OFF_K + Bki[i] * LNN_ARR + j * LNN_P + r0);
                fma4(v, dt * Bc[i], kv);
            }
            *reinterpret_cast<float4*>(yb + j * LNN_P + r0) = v;
        }
    }

    // ---- out = yT @ Wout + bout ----
    __syncthreads();
    if (cg < LNN_DOUT) {
        float4 acc = make_float4(0.f, 0.f, 0.f, 0.f);
#pragma unroll 8
        for (int k = 0; k < LNN_L; ++k) {
            float4 yv = *reinterpret_cast<const float4*>(yb + k * LNN_P + r0);
            float w = sm[OFF_WOUT + k * LNN_DOUT + cg];
            fma4(acc, w, yv);
        }
        float bo = sm[OFF_BOUT + cg];
        float vals[4] = {acc.x + bo, acc.y + bo, acc.z + bo, acc.w + bo};
#pragma unroll
        for (int b = 0; b < 4; ++b) {
            int row = rowbase + r0 + b;
            if (row < B) out[(size_t)row * LNN_DOUT + cg] = vals[b];
        }
    }
}

extern "C" void kernel_launch(void* const* d_in, const int* in_sizes, int n_in,
                              void* d_out, int out_size) {
    const float* x    = (const float*)d_in[0];
    const float* ts   = (const float*)d_in[1];
    const float* Win  = (const float*)d_in[2];
    const float* bin  = (const float*)d_in[3];
    const float* W1   = (const float*)d_in[4];
    const float* b1   = (const float*)d_in[5];
    const float* W2   = (const float*)d_in[6];
    const float* b2   = (const float*)d_in[7];
    const float* Wout = (const float*)d_in[8];
    const float* bout = (const float*)d_in[9];
    float* out = (float*)d_out;

    int B = in_sizes[0] / LNN_DIN;
    cudaFuncSetAttribute(lnn2276_kernel,
                         cudaFuncAttributeMaxDynamicSharedMemorySize, SMEM_BYTES);
    int grid = (B + LNN_R - 1) / LNN_R;
    lnn2276_kernel<<<grid, LNN_NT, SMEM_BYTES>>>(x, ts, Win, bin, W1, b1, W2, b2,
                                                 Wout, bout, out, B);
}

// round 5
// speedup vs baseline: 3.4568x; 3.4568x over previous
#include <cuda_runtime.h>
#include <cuda_fp16.h>
#include <cstdint>

// ---------------------------------------------------------------------------
// LiquidNeuralNetwork via mma.sync HMMA (fp16 3-way split, fp32 accum).
// y0 = x@Win+bin; 32 DOPRI5 steps of f(y)=tanh(y@W1+b1)@W2+b2; out=yT@Wout+bout.
// CTA = 128 rows, 8 warps x 16 rows, warps fully decoupled in the main loop.
// State y + accY in registers (D-fragment layout); 5 stage-combination
// accumulators in warp-private SMEM; W frags pre-arranged in SMEM.
// ---------------------------------------------------------------------------

#define LNN_DIN    14
#define LNN_DOUT   3
#define LNN_M      128
#define LNN_NT     256
#define LNN_NW     8
#define LNN_NSTEPS 32

// SMEM byte offsets
#define OFF_W1H   0            // frag-order: [4 kt][8 j][32 lane] x uint2 = 8192 B
#define OFF_W1L   8192
#define OFF_W2H   16384
#define OFF_W2L   24576
#define OFF_ACC   32768        // 5 arrays x [8 w][8 j][32 lane] x float4 = 5*32768
#define OFF_WIN   196608       // 14*64 f32
#define OFF_BIN   200192       // 64 f32
#define OFF_B1    200448
#define OFF_B2    200704
#define OFF_WOUT  200960       // 64*3 f32
#define OFF_BOUT  201728
#define OFF_CT    201744       // C[6][5] f32
#define OFF_BC    201864       // bc[6] f32
#define SMEM_SZ   201984

__device__ __forceinline__ void mma8(float* d, uint32_t a0, uint32_t a1,
                                     uint32_t a2, uint32_t a3, uint2 b) {
    asm("mma.sync.aligned.m16n8k16.row.col.f32.f16.f16.f32 "
        "{%0,%1,%2,%3}, {%4,%5,%6,%7}, {%8,%9}, {%0,%1,%2,%3};"
        : "+f"(d[0]), "+f"(d[1]), "+f"(d[2]), "+f"(d[3])
        : "r"(a0), "r"(a1), "r"(a2), "r"(a3), "r"(b.x), "r"(b.y));
}

__device__ __forceinline__ void pack_hilo(float a, float b,
                                          uint32_t& h, uint32_t& l) {
    __half2 H = __floats2half2_rn(a, b);
    float2 f = __half22float2(H);
    __half2 L = __floats2half2_rn(a - f.x, b - f.y);
    h = *reinterpret_cast<uint32_t*>(&H);
    l = *reinterpret_cast<uint32_t*>(&L);
}

__device__ __forceinline__ float fast_tanh(float x) {
    float ax = fabsf(x);
    float e  = __expf(-2.0f * ax);
    float t  = __fdividef(1.0f - e, 1.0f + e);
    return copysignf(t, x);
}

// D += A(hi/lo) @ W(hi/lo), K=64, N=64.  D[32] = 8 n-tiles x 4.
__device__ __forceinline__ void gemm64(float* D,
                                       const uint32_t* AH, const uint32_t* AL,
                                       const char* WH, const char* WL, int lane) {
#pragma unroll
    for (int i = 0; i < 32; ++i) D[i] = 0.0f;
#pragma unroll
    for (int kt = 0; kt < 4; ++kt) {
        const uint2* bh = reinterpret_cast<const uint2*>(WH) + kt * 256 + lane;
        const uint2* bl = reinterpret_cast<const uint2*>(WL) + kt * 256 + lane;
#pragma unroll
        for (int j = 0; j < 8; ++j) {
            uint2 b = bh[j * 32];
            mma8(D + 4 * j, AH[4*kt], AH[4*kt+1], AH[4*kt+2], AH[4*kt+3], b);
            mma8(D + 4 * j, AL[4*kt], AL[4*kt+1], AL[4*kt+2], AL[4*kt+3], b);
        }
#pragma unroll
        for (int j = 0; j < 8; ++j) {
            uint2 b = bl[j * 32];
            mma8(D + 4 * j, AH[4*kt], AH[4*kt+1], AH[4*kt+2], AH[4*kt+3], b);
        }
    }
}

__global__ __launch_bounds__(LNN_NT)
void lnn2276_hmma_kernel(const float* __restrict__ x,
                         const float* __restrict__ ts,
                         const float* __restrict__ gWin, const float* __restrict__ gbin,
                         const float* __restrict__ gW1,  const float* __restrict__ gb1,
                         const float* __restrict__ gW2,  const float* __restrict__ gb2,
                         const float* __restrict__ gWout, const float* __restrict__ gbout,
                         float* __restrict__ out, int B) {
    extern __shared__ char sm[];
    const int tid  = threadIdx.x;
    const int w    = tid >> 5;
    const int lane = tid & 31;
    const int g    = lane >> 2;    // row group 0..7
    const int tig  = lane & 3;     // thread-in-group

    // ---- prologue: build W fragments (hi/lo fp16) in frag order ----
    for (int p = tid; p < 1024; p += LNN_NT) {
        int kt = p >> 8, j = (p >> 5) & 7, ln = p & 31;
        int tg = ln & 3, gg = ln >> 2;
        int k0 = kt * 16 + 2 * tg;
        int n  = 8 * j + gg;
        float a0 = gW1[k0 * 64 + n],       a1 = gW1[(k0 + 1) * 64 + n];
        float a2 = gW1[(k0 + 8) * 64 + n], a3 = gW1[(k0 + 9) * 64 + n];
        uint32_t h0, l0, h1, l1;
        pack_hilo(a0, a1, h0, l0);
        pack_hilo(a2, a3, h1, l1);
        *reinterpret_cast<uint2*>(sm + OFF_W1H + p * 8) = make_uint2(h0, h1);
        *reinterpret_cast<uint2*>(sm + OFF_W1L + p * 8) = make_uint2(l0, l1);
        a0 = gW2[k0 * 64 + n];       a1 = gW2[(k0 + 1) * 64 + n];
        a2 = gW2[(k0 + 8) * 64 + n]; a3 = gW2[(k0 + 9) * 64 + n];
        pack_hilo(a0, a1, h0, l0);
        pack_hilo(a2, a3, h1, l1);
        *reinterpret_cast<uint2*>(sm + OFF_W2H + p * 8) = make_uint2(h0, h1);
        *reinterpret_cast<uint2*>(sm + OFF_W2L + p * 8) = make_uint2(l0, l1);
    }
    for (int i = tid; i < LNN_DIN * 64; i += LNN_NT)
        *(float*)(sm + OFF_WIN + i * 4) = gWin[i];
    for (int i = tid; i < 64 * LNN_DOUT; i += LNN_NT)
        *(float*)(sm + OFF_WOUT + i * 4) = gWout[i];
    if (tid < 64) {
        *(float*)(sm + OFF_BIN + tid * 4) = gbin[tid];
        *(float*)(sm + OFF_B1 + tid * 4)  = gb1[tid];
        *(float*)(sm + OFF_B2 + tid * 4)  = gb2[tid];
    }
    if (tid < LNN_DOUT) *(float*)(sm + OFF_BOUT + tid * 4) = gbout[tid];
    if (tid == 0) {
        float* C = (float*)(sm + OFF_CT);
        for (int i = 0; i < 30; ++i) C[i] = 0.0f;
        C[0] = (float)(1.0/5.0);       C[1] = (float)(3.0/40.0);
        C[2] = (float)(44.0/45.0);     C[3] = (float)(19372.0/6561.0);
        C[4] = (float)(9017.0/3168.0);
        C[5+1] = (float)(9.0/40.0);    C[5+2] = (float)(-56.0/15.0);
        C[5+3] = (float)(-25360.0/2187.0); C[5+4] = (float)(-355.0/33.0);
        C[10+2] = (float)(32.0/9.0);   C[10+3] = (float)(64448.0/6561.0);
        C[10+4] = (float)(46732.0/5247.0);
        C[15+3] = (float)(-212.0/729.0); C[15+4] = (float)(49.0/176.0);
        C[20+4] = (float)(-5103.0/18656.0);
        float* bc = (float*)(sm + OFF_BC);
        bc[0] = (float)(35.0/384.0);  bc[1] = 0.0f;
        bc[2] = (float)(500.0/1113.0); bc[3] = (float)(125.0/192.0);
        bc[4] = (float)(-2187.0/6784.0); bc[5] = (float)(11.0/84.0);
    }
    __syncthreads();

    const float dt = (ts[1] - ts[0]) * (1.0f / (float)LNN_NSTEPS);
    const int r1 = blockIdx.x * LNN_M + w * 16 + g;   // rows this thread owns
    const int r2 = r1 + 8;

    // ---- y0 = x @ Win + bin, directly in D-fragment layout ----
    float y[32];
    {
        float xr1[LNN_DIN], xr2[LNN_DIN];
#pragma unroll
        for (int k = 0; k < LNN_DIN; ++k) {
            xr1[k] = (r1 < B) ? x[(size_t)r1 * LNN_DIN + k] : 0.0f;
            xr2[k] = (r2 < B) ? x[(size_t)r2 * LNN_DIN + k] : 0.0f;
        }
#pragma unroll
        for (int j = 0; j < 8; ++j) {
            int c0 = 8 * j + 2 * tig;
            float s0 = *(const float*)(sm + OFF_BIN + c0 * 4);
            float s1 = *(const float*)(sm + OFF_BIN + (c0 + 1) * 4);
            float a0 = s0, a1 = s1, a2 = s0, a3 = s1;
#pragma unroll
            for (int k = 0; k < LNN_DIN; ++k) {
                float w0 = *(const float*)(sm + OFF_WIN + (k * 64 + c0) * 4);
                float w1 = *(const float*)(sm + OFF_WIN + (k * 64 + c0 + 1) * 4);
                a0 = fmaf(xr1[k], w0, a0);
                a1 = fmaf(xr1[k], w1, a1);
                a2 = fmaf(xr2[k], w0, a2);
                a3 = fmaf(xr2[k], w1, a3);
            }
            y[4*j+0] = a0; y[4*j+1] = a1; y[4*j+2] = a2; y[4*j+3] = a3;
        }
    }

    // per-thread ACC addressing: arr m, this warp, n-tile j, this lane
    const int accSlice = (w * 8 * 32 + lane) * 16;   // + m*32768 + j*512
    const float* Ct  = (const float*)(sm + OFF_CT);
    const float* bct = (const float*)(sm + OFF_BC);

    float accY[32];
    uint32_t AH[16], AL[16];
    float D[32];

#pragma unroll 1
    for (int step = 0; step < LNN_NSTEPS; ++step) {
#pragma unroll 1
        for (int s = 0; s < 6; ++s) {
            // ---- build u = y (+ dt*arr[s-1]) into A frags ----
            const char* ab = sm + OFF_ACC + (s - 1) * 32768 + accSlice;
#pragma unroll
            for (int j = 0; j < 8; ++j) {
                float4 av = make_float4(0.f, 0.f, 0.f, 0.f);
                if (s > 0) av = *(const float4*)(ab + j * 512);
                float u0 = fmaf(dt, av.x, y[4*j+0]);
                float u1 = fmaf(dt, av.y, y[4*j+1]);
                float u2 = fmaf(dt, av.z, y[4*j+2]);
                float u3 = fmaf(dt, av.w, y[4*j+3]);
                int t4 = 4 * (j >> 1) + 2 * (j & 1);
                pack_hilo(u0, u1, AH[t4], AL[t4]);
                pack_hilo(u2, u3, AH[t4+1], AL[t4+1]);
            }
            // ---- GEMM1 + tanh ----
            gemm64(D, AH, AL, sm + OFF_W1H, sm + OFF_W1L, lane);
#pragma unroll
            for (int j = 0; j < 8; ++j) {
                float2 bb = *(const float2*)(sm + OFF_B1 + (8*j + 2*tig) * 4);
                float t0 = fast_tanh(D[4*j+0] + bb.x);
                float t1 = fast_tanh(D[4*j+1] + bb.y);
                float t2 = fast_tanh(D[4*j+2] + bb.x);
                float t3 = fast_tanh(D[4*j+3] + bb.y);
                int t4 = 4 * (j >> 1) + 2 * (j & 1);
                pack_hilo(t0, t1, AH[t4], AL[t4]);
                pack_hilo(t2, t3, AH[t4+1], AL[t4+1]);
            }
            // ---- GEMM2 + bias -> k (in D) ----
            gemm64(D, AH, AL, sm + OFF_W2H, sm + OFF_W2L, lane);
#pragma unroll
            for (int j = 0; j < 8; ++j) {
                float2 bb = *(const float2*)(sm + OFF_B2 + (8*j + 2*tig) * 4);
                D[4*j+0] += bb.x; D[4*j+1] += bb.y;
                D[4*j+2] += bb.x; D[4*j+3] += bb.y;
            }
            // ---- accY and stage-combination accumulators ----
            float bcs = bct[s];
#pragma unroll
            for (int i = 0; i < 32; ++i)
                accY[i] = fmaf(bcs, D[i], (s == 0) ? 0.0f : accY[i]);
            for (int m = s; m < 5; ++m) {
                float c = Ct[s * 5 + m];
                char* mb = sm + OFF_ACC + m * 32768 + accSlice;
#pragma unroll
                for (int j = 0; j < 8; ++j) {
                    float4 v = make_float4(0.f, 0.f, 0.f, 0.f);
                    if (s > 0) v = *(const float4*)(mb + j * 512);
                    v.x = fmaf(c, D[4*j+0], v.x);
                    v.y = fmaf(c, D[4*j+1], v.y);
                    v.z = fmaf(c, D[4*j+2], v.z);
                    v.w = fmaf(c, D[4*j+3], v.w);
                    *(float4*)(mb + j * 512) = v;
                }
            }
        }
        // ---- y += dt * accY ----
#pragma unroll
        for (int i = 0; i < 32; ++i) y[i] = fmaf(dt, accY[i], y[i]);
    }

    // ---- out = y @ Wout + bout (reduce across tig quad via shfl) ----
    {
        float o1[LNN_DOUT] = {0.f, 0.f, 0.f};
        float o2[LNN_DOUT] = {0.f, 0.f, 0.f};
#pragma unroll
        for (int j = 0; j < 8; ++j) {
#pragma unroll
            for (int e = 0; e < 2; ++e) {
                int col = 8 * j + 2 * tig + e;
#pragma unroll
                for (int q = 0; q < LNN_DOUT; ++q) {
                    float wv = *(const float*)(sm + OFF_WOUT + (col * LNN_DOUT + q) * 4);
                    o1[q] = fmaf(y[4*j+e],     wv, o1[q]);
                    o2[q] = fmaf(y[4*j+2+e],   wv, o2[q]);
                }
            }
        }
#pragma unroll
        for (int q = 0; q < LNN_DOUT; ++q) {
            o1[q] += __shfl_xor_sync(0xffffffffu, o1[q], 1);
            o1[q] += __shfl_xor_sync(0xffffffffu, o1[q], 2);
            o2[q] += __shfl_xor_sync(0xffffffffu, o2[q], 1);
            o2[q] += __shfl_xor_sync(0xffffffffu, o2[q], 2);
        }
        if (tig == 0) {
#pragma unroll
            for (int q = 0; q < LNN_DOUT; ++q) {
                float bo = *(const float*)(sm + OFF_BOUT + q * 4);
                if (r1 < B) out[(size_t)r1 * LNN_DOUT + q] = o1[q] + bo;
                if (r2 < B) out[(size_t)r2 * LNN_DOUT + q] = o2[q] + bo;
            }
        }
    }
}

extern "C" void kernel_launch(void* const* d_in, const int* in_sizes, int n_in,
                              void* d_out, int out_size) {
    const float* x    = (const float*)d_in[0];
    const float* ts   = (const float*)d_in[1];
    const float* Win  = (const float*)d_in[2];
    const float* bin  = (const float*)d_in[3];
    const float* W1   = (const float*)d_in[4];
    const float* b1   = (const float*)d_in[5];
    const float* W2   = (const float*)d_in[6];
    const float* b2   = (const float*)d_in[7];
    const float* Wout = (const float*)d_in[8];
    const float* bout = (const float*)d_in[9];
    float* out = (float*)d_out;

    int B = in_sizes[0] / LNN_DIN;
    cudaFuncSetAttribute(lnn2276_hmma_kernel,
                         cudaFuncAttributeMaxDynamicSharedMemorySize, SMEM_SZ);
    int grid = (B + LNN_M - 1) / LNN_M;
    lnn2276_hmma_kernel<<<grid, LNN_NT, SMEM_SZ>>>(x, ts, Win, bin, W1, b1, W2, b2,
                                                   Wout, bout, out, B);
}